// round 1
// baseline (speedup 1.0000x reference)
#include <cuda_runtime.h>
#include <cstdint>
#include <math.h>

// ---------------------------------------------------------------------------
// KoopmanAE: 4 GEMMs with fused epilogues, TF32 tensor cores (mma.sync m16n8k8)
//   L1: h1   = tanh(x @ W_enc1 + b_enc1)          [8192,4096]x[4096,4096]
//   L2: encx = h1 @ W_enc2 + b_enc2               [8192,4096]x[4096,2048]
//       encp = koopman_rotate(encx, dt, amp, frq) (fused epilogue)
//   L3: h2   = tanh(encp @ W_dec1 + b_dec1)       [8192,2048]x[2048,4096]
//   L4: full = h2 @ W_dec2 + b_dec2               [8192,4096]x[4096,4096]
// Output tuple layout in d_out: [full_pred | enc_pred | enc_x]
// ---------------------------------------------------------------------------

#define BM 128
#define BN 128
#define BK 32
#define NTHREADS 256

#define AS_LD 36     // A_s row stride (floats): bank = (4*m + k) % 32 -> conflict-free frags
#define BS_LD 136    // B_s row stride (floats): bank = (8*k + n) % 32 -> conflict-free frags
#define AS_SIZE (BM * AS_LD)
#define BS_SIZE (BK * BS_LD)

// 128 MB scratch, reused: h1 (L1 out / L2 in), then h2 (L3 out / L4 in)
__device__ float g_scratch[8192u * 4096u];

__device__ __forceinline__ uint32_t f2tf32(float x) {
    uint32_t r;
    asm("cvt.rna.tf32.f32 %0, %1;" : "=r"(r) : "f"(x));
    return r;
}

__device__ __forceinline__ void mma_m16n8k8(float d[4], const uint32_t a[4], const uint32_t b[2]) {
    asm("mma.sync.aligned.m16n8k8.row.col.f32.tf32.tf32.f32 "
        "{%0,%1,%2,%3}, {%4,%5,%6,%7}, {%8,%9}, {%0,%1,%2,%3};"
        : "+f"(d[0]), "+f"(d[1]), "+f"(d[2]), "+f"(d[3])
        : "r"(a[0]), "r"(a[1]), "r"(a[2]), "r"(a[3]), "r"(b[0]), "r"(b[1]));
}

// MODE 0: C = tanh(acc + bias)
// MODE 1: C = acc + bias (enc_x), C2 = koopman rotation of C (enc_pred)
// MODE 2: C = acc + bias
template <int MODE>
__global__ void __launch_bounds__(NTHREADS, 1)
gemm_tf32(const float* __restrict__ A, const float* __restrict__ W,
          const float* __restrict__ bias, float* __restrict__ C,
          float* __restrict__ C2,
          const float* __restrict__ dt, const float* __restrict__ amps,
          const float* __restrict__ freqs,
          int M, int N, int K)
{
    extern __shared__ uint32_t smem[];
    uint32_t* As = smem;                  // 2 stages of [BM][AS_LD]
    uint32_t* Bs = smem + 2 * AS_SIZE;    // 2 stages of [BK][BS_LD]

    const int tid    = threadIdx.x;
    const int warp   = tid >> 5;
    const int lane   = tid & 31;
    const int g      = lane >> 2;   // groupID 0..7
    const int t      = lane & 3;    // threadID_in_group 0..3
    const int warp_m = warp >> 2;   // 0..1  (64 rows each)
    const int warp_n = warp & 3;    // 0..3  (32 cols each)

    const int bm = blockIdx.y;
    const int bn = blockIdx.x;

    // ---- global load mapping: 4 x float4 per thread for A and B per stage ----
    const float* pA[4];
    const float* pB[4];
    int sA[4], sB[4];
#pragma unroll
    for (int i = 0; i < 4; ++i) {
        int li = tid + i * NTHREADS;            // 0..1023
        int ar = li >> 3;                       // 0..127
        int ac = (li & 7) * 4;                  // 0..28
        pA[i] = A + (size_t)(bm * BM + ar) * K + ac;
        sA[i] = ar * AS_LD + ac;
        int br = li >> 5;                       // 0..31
        int bc = (li & 31) * 4;                 // 0..124
        pB[i] = W + (size_t)br * N + bn * BN + bc;
        sB[i] = br * BS_LD + bc;
    }

    const int niter = K / BK;

    float4 ra[4], rb[4];

    // prologue: tile 0 -> stage 0
#pragma unroll
    for (int i = 0; i < 4; ++i) { ra[i] = *(const float4*)pA[i]; rb[i] = *(const float4*)pB[i]; }
#pragma unroll
    for (int i = 0; i < 4; ++i) {
        uint4 va = make_uint4(f2tf32(ra[i].x), f2tf32(ra[i].y), f2tf32(ra[i].z), f2tf32(ra[i].w));
        *(uint4*)(As + sA[i]) = va;
        uint4 vb = make_uint4(f2tf32(rb[i].x), f2tf32(rb[i].y), f2tf32(rb[i].z), f2tf32(rb[i].w));
        *(uint4*)(Bs + sB[i]) = vb;
    }
    __syncthreads();

    float acc[4][4][4];
#pragma unroll
    for (int mi = 0; mi < 4; ++mi)
#pragma unroll
        for (int ni = 0; ni < 4; ++ni)
#pragma unroll
            for (int r = 0; r < 4; ++r) acc[mi][ni][r] = 0.0f;

    for (int it = 0; it < niter; ++it) {
        const int stage = it & 1;
        const bool has_next = (it + 1) < niter;

        if (has_next) {
#pragma unroll
            for (int i = 0; i < 4; ++i) {
                pA[i] += BK;
                pB[i] += (size_t)BK * N;
                ra[i] = *(const float4*)pA[i];
                rb[i] = *(const float4*)pB[i];
            }
        }

        // ---- compute current stage ----
        const uint32_t* asw = As + stage * AS_SIZE + (warp_m * 64 + g) * AS_LD + t;
        const uint32_t* bsw = Bs + stage * BS_SIZE + t * BS_LD + warp_n * 32 + g;

#pragma unroll
        for (int ks = 0; ks < BK / 8; ++ks) {
            const int kk = ks * 8;
            uint32_t af[4][4], bf[4][2];
#pragma unroll
            for (int mi = 0; mi < 4; ++mi) {
                const uint32_t* p = asw + mi * 16 * AS_LD + kk;
                af[mi][0] = p[0];
                af[mi][1] = p[8 * AS_LD];
                af[mi][2] = p[4];
                af[mi][3] = p[8 * AS_LD + 4];
            }
#pragma unroll
            for (int ni = 0; ni < 4; ++ni) {
                const uint32_t* p = bsw + kk * BS_LD + ni * 8;
                bf[ni][0] = p[0];
                bf[ni][1] = p[4 * BS_LD];
            }
#pragma unroll
            for (int mi = 0; mi < 4; ++mi)
#pragma unroll
                for (int ni = 0; ni < 4; ++ni)
                    mma_m16n8k8(acc[mi][ni], af[mi], bf[ni]);
        }

        if (has_next) {
            const int nstage = (it + 1) & 1;
#pragma unroll
            for (int i = 0; i < 4; ++i) {
                uint4 va = make_uint4(f2tf32(ra[i].x), f2tf32(ra[i].y), f2tf32(ra[i].z), f2tf32(ra[i].w));
                *(uint4*)(As + nstage * AS_SIZE + sA[i]) = va;
                uint4 vb = make_uint4(f2tf32(rb[i].x), f2tf32(rb[i].y), f2tf32(rb[i].z), f2tf32(rb[i].w));
                *(uint4*)(Bs + nstage * BS_SIZE + sB[i]) = vb;
            }
        }
        __syncthreads();
    }

    // ---- epilogue ----
    const int row_base = bm * BM + warp_m * 64;
    const int col_base = bn * BN + warp_n * 32;

#pragma unroll
    for (int mi = 0; mi < 4; ++mi) {
        const int r0 = row_base + mi * 16 + g;
        const int r1 = r0 + 8;
        float dt0 = 0.f, dt1 = 0.f;
        if (MODE == 1) { dt0 = dt[r0]; dt1 = dt[r1]; }
#pragma unroll
        for (int ni = 0; ni < 4; ++ni) {
            const int c = col_base + ni * 8 + 2 * t;
            const float bv0 = bias[c];
            const float bv1 = bias[c + 1];
            float v00 = acc[mi][ni][0] + bv0;
            float v01 = acc[mi][ni][1] + bv1;
            float v10 = acc[mi][ni][2] + bv0;
            float v11 = acc[mi][ni][3] + bv1;

            if (MODE == 0) {
                v00 = tanhf(v00); v01 = tanhf(v01);
                v10 = tanhf(v10); v11 = tanhf(v11);
            }

            *(float2*)(C + (size_t)r0 * N + c) = make_float2(v00, v01);
            *(float2*)(C + (size_t)r1 * N + c) = make_float2(v10, v11);

            if (MODE == 1) {
                const int f = c >> 1;
                const float af = amps[f];
                const float wf = freqs[f];
                // row r0
                {
                    float amp = __powf(af, dt0);
                    float s, co;
                    sincosf(wf * dt0, &s, &co);
                    float cs = amp * co, ss = amp * s;
                    *(float2*)(C2 + (size_t)r0 * N + c) =
                        make_float2(cs * v00 - ss * v01, ss * v00 + cs * v01);
                }
                // row r1
                {
                    float amp = __powf(af, dt1);
                    float s, co;
                    sincosf(wf * dt1, &s, &co);
                    float cs = amp * co, ss = amp * s;
                    *(float2*)(C2 + (size_t)r1 * N + c) =
                        make_float2(cs * v10 - ss * v11, ss * v10 + cs * v11);
                }
            }
        }
    }
}

extern "C" void kernel_launch(void* const* d_in, const int* in_sizes, int n_in,
                              void* d_out, int out_size)
{
    const float* x     = (const float*)d_in[0];
    const float* dt    = (const float*)d_in[1];
    const float* W1    = (const float*)d_in[2];
    const float* b1    = (const float*)d_in[3];
    const float* W2    = (const float*)d_in[4];
    const float* b2    = (const float*)d_in[5];
    const float* amps  = (const float*)d_in[6];
    const float* freqs = (const float*)d_in[7];
    const float* W3    = (const float*)d_in[8];
    const float* b3    = (const float*)d_in[9];
    const float* W4    = (const float*)d_in[10];
    const float* b4    = (const float*)d_in[11];
    float* out = (float*)d_out;

    const int Bn = 8192, DIN = 4096, HID = 4096, TWOF = 2048;

    float* full = out;                                 // [B, DIN]
    float* encp = out + (size_t)Bn * DIN;              // [B, 2F]
    float* encx = encp + (size_t)Bn * TWOF;            // [B, 2F]

    float* scratch = nullptr;
    cudaGetSymbolAddress((void**)&scratch, g_scratch); // h1 then h2

    const size_t smem_bytes = (size_t)2 * (AS_SIZE + BS_SIZE) * sizeof(uint32_t); // 71680
    cudaFuncSetAttribute(gemm_tf32<0>, cudaFuncAttributeMaxDynamicSharedMemorySize, (int)smem_bytes);
    cudaFuncSetAttribute(gemm_tf32<1>, cudaFuncAttributeMaxDynamicSharedMemorySize, (int)smem_bytes);
    cudaFuncSetAttribute(gemm_tf32<2>, cudaFuncAttributeMaxDynamicSharedMemorySize, (int)smem_bytes);

    dim3 blk(NTHREADS);

    // L1: h1 = tanh(x @ W1 + b1)
    gemm_tf32<0><<<dim3(HID / BN, Bn / BM), blk, smem_bytes>>>(
        x, W1, b1, scratch, nullptr, nullptr, nullptr, nullptr, Bn, HID, DIN);

    // L2: encx = h1 @ W2 + b2 ; encp = rotate(encx)
    gemm_tf32<1><<<dim3(TWOF / BN, Bn / BM), blk, smem_bytes>>>(
        scratch, W2, b2, encx, encp, dt, amps, freqs, Bn, TWOF, HID);

    // L3: h2 = tanh(encp @ W3 + b3)   (reads enc_pred from d_out, reuses scratch)
    gemm_tf32<0><<<dim3(HID / BN, Bn / BM), blk, smem_bytes>>>(
        encp, W3, b3, scratch, nullptr, nullptr, nullptr, nullptr, Bn, HID, TWOF);

    // L4: full = h2 @ W4 + b4
    gemm_tf32<2><<<dim3(DIN / BN, Bn / BM), blk, smem_bytes>>>(
        scratch, W4, b4, full, nullptr, nullptr, nullptr, nullptr, Bn, DIN, HID);
}